// round 2
// baseline (speedup 1.0000x reference)
#include <cuda_runtime.h>

#define N_NODES 50000
#define N_EDGES 800000
#define F_IN    256
#define F_HID   128
#define F_OUT   40

// Scratch (no allocation allowed in kernel_launch)
__device__ float g_deg [N_NODES];
__device__ float g_dinv[N_NODES];
__device__ float g_h   [N_NODES * F_HID];   // layer1 linear output
__device__ float g_agg1[N_NODES * F_HID];   // layer1 aggregation accumulator
__device__ float g_h2  [N_NODES * F_OUT];   // layer2 linear output (gather source)

// ---------------------------------------------------------------------------
// degree / normalization
// ---------------------------------------------------------------------------
__global__ void init_deg_kernel(int n) {
    int i = blockIdx.x * blockDim.x + threadIdx.x;
    if (i < n) g_deg[i] = 1.0f;               // self-loop weight
}

__global__ void deg_edges_kernel(const int* __restrict__ col,
                                 const float* __restrict__ ew, int ne) {
    int i = blockIdx.x * blockDim.x + threadIdx.x;
    if (i < ne) atomicAdd(&g_deg[col[i]], ew[i]);
}

__global__ void dinv_kernel(int n) {
    int i = blockIdx.x * blockDim.x + threadIdx.x;
    if (i < n) {
        float d = g_deg[i];
        g_dinv[i] = (d > 0.0f) ? rsqrtf(d) : 0.0f;
    }
}

// ---------------------------------------------------------------------------
// Tiled fp32 GEMM: C = A[M,KTOT] @ B[KTOT,NACT]
// Epilogue writes C (raw linear output) and C2 = C * dinv[row]^2 (+ bias),
// the self-loop contribution that initializes the aggregation buffer.
// ---------------------------------------------------------------------------
template<int BM, int BN, int BK, int KTOT, int NACT, bool HAS_BIAS>
__global__ void gemm_selfloop_kernel(const float* __restrict__ A,
                                     const float* __restrict__ B,
                                     float* __restrict__ C,
                                     float* __restrict__ C2,
                                     const float* __restrict__ bias,
                                     int M)
{
    __shared__ float As[BM][BK + 1];
    __shared__ float Bs[BK][BN];
    constexpr int TM = BM / 16;
    constexpr int TN = BN / 16;

    const int tid = threadIdx.x;          // 256 threads, 16x16 layout
    const int tr  = tid >> 4;
    const int tc  = tid & 15;
    const int m0  = blockIdx.x * BM;

    float acc[TM][TN];
    #pragma unroll
    for (int i = 0; i < TM; ++i)
        #pragma unroll
        for (int j = 0; j < TN; ++j) acc[i][j] = 0.0f;

    for (int k0 = 0; k0 < KTOT; k0 += BK) {
        #pragma unroll
        for (int t = 0; t < BM * BK / 256; ++t) {
            int idx = tid + t * 256;
            int r = idx / BK, kk = idx % BK;
            int gr = m0 + r;
            As[r][kk] = (gr < M) ? A[(size_t)gr * KTOT + k0 + kk] : 0.0f;
        }
        #pragma unroll
        for (int t = 0; t < BK * BN / 256; ++t) {
            int idx = tid + t * 256;
            int kk = idx / BN, c = idx % BN;
            Bs[kk][c] = (c < NACT) ? B[(size_t)(k0 + kk) * NACT + c] : 0.0f;
        }
        __syncthreads();

        #pragma unroll
        for (int kk = 0; kk < BK; ++kk) {
            float a[TM], b[TN];
            #pragma unroll
            for (int i = 0; i < TM; ++i) a[i] = As[tr + i * 16][kk];
            #pragma unroll
            for (int j = 0; j < TN; ++j) b[j] = Bs[kk][tc + j * 16];
            #pragma unroll
            for (int i = 0; i < TM; ++i)
                #pragma unroll
                for (int j = 0; j < TN; ++j)
                    acc[i][j] += a[i] * b[j];
        }
        __syncthreads();
    }

    #pragma unroll
    for (int i = 0; i < TM; ++i) {
        int row = m0 + tr + i * 16;
        if (row >= M) continue;
        float g  = g_dinv[row];
        float gg = g * g;
        #pragma unroll
        for (int j = 0; j < TN; ++j) {
            int ccol = tc + j * 16;
            if (ccol < NACT) {
                float v = acc[i][j];
                size_t idx = (size_t)row * NACT + ccol;
                C[idx] = v;
                float w = v * gg;
                if (HAS_BIAS) w += bias[ccol];
                C2[idx] = w;
            }
        }
    }
}

// ---------------------------------------------------------------------------
// Edge aggregation: out[col] += h[row] * (dinv[row]*ew*dinv[col])
// One warp per edge.
// ---------------------------------------------------------------------------
__global__ void agg128_kernel(const int* __restrict__ row,
                              const int* __restrict__ col,
                              const float* __restrict__ ew,
                              const float* __restrict__ h,
                              float* __restrict__ out, int ne)
{
    int warp = (blockIdx.x * blockDim.x + threadIdx.x) >> 5;
    int lane = threadIdx.x & 31;
    if (warp >= ne) return;
    int r = row[warp];
    int c = col[warp];
    float coef = g_dinv[r] * ew[warp] * g_dinv[c];
    const float4 v = ((const float4*)(h + (size_t)r * F_HID))[lane];
    float* o = out + (size_t)c * F_HID + lane * 4;
    atomicAdd(o + 0, v.x * coef);
    atomicAdd(o + 1, v.y * coef);
    atomicAdd(o + 2, v.z * coef);
    atomicAdd(o + 3, v.w * coef);
}

__global__ void agg40_kernel(const int* __restrict__ row,
                             const int* __restrict__ col,
                             const float* __restrict__ ew,
                             const float* __restrict__ h,
                             float* __restrict__ out, int ne)
{
    int warp = (blockIdx.x * blockDim.x + threadIdx.x) >> 5;
    int lane = threadIdx.x & 31;
    if (warp >= ne) return;
    int r = row[warp];
    int c = col[warp];
    float coef = g_dinv[r] * ew[warp] * g_dinv[c];
    const float* hr = h + (size_t)r * F_OUT;
    float* o = out + (size_t)c * F_OUT;
    atomicAdd(o + lane, hr[lane] * coef);
    if (lane < F_OUT - 32)
        atomicAdd(o + 32 + lane, hr[32 + lane] * coef);
}

// ---------------------------------------------------------------------------
// relu(agg1 + b1) -> g_h (reuse)
// ---------------------------------------------------------------------------
__global__ void relu_bias_kernel(const float* __restrict__ in,
                                 const float* __restrict__ b,
                                 float* __restrict__ out, int n)
{
    int i = blockIdx.x * blockDim.x + threadIdx.x;
    if (i < n) {
        float v = in[i] + b[i & (F_HID - 1)];
        out[i] = fmaxf(v, 0.0f);
    }
}

// ---------------------------------------------------------------------------
extern "C" void kernel_launch(void* const* d_in, const int* in_sizes, int n_in,
                              void* d_out, int out_size)
{
    const float* x   = (const float*)d_in[0];
    const int*   ei  = (const int*)d_in[1];      // int64 in reference -> int32 on device
    const float* ew  = (const float*)d_in[2];
    const float* b1  = (const float*)d_in[4];
    const float* W1  = (const float*)d_in[3];
    const float* W2  = (const float*)d_in[5];
    const float* b2  = (const float*)d_in[6];
    float*       out = (float*)d_out;

    const int* row = ei;              // edge_index[0]
    const int* col = ei + N_EDGES;    // edge_index[1]

    float *p_h, *p_agg1, *p_h2;
    cudaGetSymbolAddress((void**)&p_h,    g_h);
    cudaGetSymbolAddress((void**)&p_agg1, g_agg1);
    cudaGetSymbolAddress((void**)&p_h2,   g_h2);

    const int T = 256;

    // normalization
    init_deg_kernel<<<(N_NODES + T - 1) / T, T>>>(N_NODES);
    deg_edges_kernel<<<(N_EDGES + T - 1) / T, T>>>(col, ew, N_EDGES);
    dinv_kernel<<<(N_NODES + T - 1) / T, T>>>(N_NODES);

    // layer 1: h = x@W1 ; agg1 = h*dinv^2 (self-loop init)
    gemm_selfloop_kernel<64, 128, 32, F_IN, F_HID, false>
        <<<(N_NODES + 63) / 64, 256>>>(x, W1, p_h, p_agg1, nullptr, N_NODES);

    // edge aggregation into agg1 (1 warp / edge)
    agg128_kernel<<<(int)((N_EDGES * 32LL + T - 1) / T), T>>>(row, col, ew, p_h, p_agg1, N_EDGES);

    // relu(agg1 + b1) -> g_h (reused)
    relu_bias_kernel<<<(N_NODES * F_HID + T - 1) / T, T>>>(p_agg1, b1, p_h, N_NODES * F_HID);

    // layer 2: h2 = relu@W2 ; d_out = h2*dinv^2 + b2 (self-loop init + bias)
    gemm_selfloop_kernel<64, 64, 32, F_HID, F_OUT, true>
        <<<(N_NODES + 63) / 64, 256>>>(p_h, W2, p_h2, out, b2, N_NODES);

    // edge aggregation into d_out
    agg40_kernel<<<(int)((N_EDGES * 32LL + T - 1) / T), T>>>(row, col, ew, p_h2, out, N_EDGES);
}

// round 3
// speedup vs baseline: 1.9701x; 1.9701x over previous
#include <cuda_runtime.h>

#define N_NODES 50000
#define N_EDGES 800000
#define F_IN    256
#define F_HID   128
#define F_OUT   40

#define SCAN_B  256
#define NB      ((N_NODES + SCAN_B - 1) / SCAN_B)   // 196

// Scratch (no allocation allowed anywhere)
__device__ float g_deg  [N_NODES];
__device__ float g_dinv [N_NODES];
__device__ int   g_cnt  [N_NODES];        // in-degree counts (int)
__device__ int   g_ptr  [N_NODES + 1];    // CSR offsets (by destination)
__device__ int   g_cur  [N_NODES];        // fill cursors
__device__ int   g_bsum [NB];
__device__ int   g_boff [NB];
__device__ int   g_rows [N_EDGES];        // source row per sorted slot
__device__ float g_coef [N_EDGES];        // dinv[r]*ew*dinv[c] per sorted slot
__device__ float g_h    [N_NODES * F_HID];   // layer1 linear output
__device__ float g_hrelu[N_NODES * F_HID];   // relu(agg1 + b1)
__device__ float g_h2   [N_NODES * F_OUT];   // layer2 linear output

// ---------------------------------------------------------------------------
// init: deg = 1 (self-loop), cnt = 0
// ---------------------------------------------------------------------------
__global__ void init_kernel() {
    int i = blockIdx.x * blockDim.x + threadIdx.x;
    if (i < N_NODES) { g_deg[i] = 1.0f; g_cnt[i] = 0; }
}

// count in-edges + weighted degree
__global__ void count_kernel(const int* __restrict__ col,
                             const float* __restrict__ ew) {
    int i = blockIdx.x * blockDim.x + threadIdx.x;
    if (i < N_EDGES) {
        int c = col[i];
        atomicAdd(&g_deg[c], ew[i]);
        atomicAdd(&g_cnt[c], 1);
    }
}

__global__ void dinv_kernel() {
    int i = blockIdx.x * blockDim.x + threadIdx.x;
    if (i < N_NODES) {
        float d = g_deg[i];
        g_dinv[i] = (d > 0.0f) ? rsqrtf(d) : 0.0f;
    }
}

// ---------------------------------------------------------------------------
// 3-pass exclusive scan of g_cnt -> g_ptr
// ---------------------------------------------------------------------------
__global__ void scan1_kernel() {
    __shared__ int s[SCAN_B];
    int i = blockIdx.x * SCAN_B + threadIdx.x;
    int v = (i < N_NODES) ? g_cnt[i] : 0;
    s[threadIdx.x] = v; __syncthreads();
    #pragma unroll
    for (int off = 1; off < SCAN_B; off <<= 1) {
        int t = (threadIdx.x >= off) ? s[threadIdx.x - off] : 0;
        __syncthreads();
        s[threadIdx.x] += t;
        __syncthreads();
    }
    if (i < N_NODES) g_ptr[i] = s[threadIdx.x] - v;   // exclusive within block
    if (threadIdx.x == SCAN_B - 1) g_bsum[blockIdx.x] = s[SCAN_B - 1];
}

__global__ void scan2_kernel() {   // one block scans the NB block sums
    __shared__ int s[SCAN_B];
    int v = (threadIdx.x < NB) ? g_bsum[threadIdx.x] : 0;
    s[threadIdx.x] = v; __syncthreads();
    #pragma unroll
    for (int off = 1; off < SCAN_B; off <<= 1) {
        int t = (threadIdx.x >= off) ? s[threadIdx.x - off] : 0;
        __syncthreads();
        s[threadIdx.x] += t;
        __syncthreads();
    }
    if (threadIdx.x < NB) g_boff[threadIdx.x] = s[threadIdx.x] - v;
}

__global__ void scan3_kernel() {
    int i = blockIdx.x * blockDim.x + threadIdx.x;
    if (i < N_NODES) {
        int p = g_ptr[i] + g_boff[i / SCAN_B];
        g_ptr[i] = p;
        g_cur[i] = p;
    }
    if (i == 0) g_ptr[N_NODES] = N_EDGES;
}

// fill CSR slots: sorted source + precomputed coefficient
__global__ void fill_kernel(const int* __restrict__ row,
                            const int* __restrict__ col,
                            const float* __restrict__ ew) {
    int e = blockIdx.x * blockDim.x + threadIdx.x;
    if (e < N_EDGES) {
        int c = col[e], r = row[e];
        int pos = atomicAdd(&g_cur[c], 1);
        g_rows[pos] = r;
        g_coef[pos] = g_dinv[r] * ew[e] * g_dinv[c];
    }
}

// ---------------------------------------------------------------------------
// Tiled fp32 GEMM: C = A[M,KTOT] @ B[KTOT,NACT]   (linear output only)
// ---------------------------------------------------------------------------
template<int BM, int BN, int BK, int KTOT, int NACT>
__global__ void gemm_kernel(const float* __restrict__ A,
                            const float* __restrict__ B,
                            float* __restrict__ C, int M)
{
    __shared__ float As[BM][BK + 1];
    __shared__ float Bs[BK][BN];
    constexpr int TM = BM / 16;
    constexpr int TN = BN / 16;

    const int tid = threadIdx.x;          // 256 threads, 16x16 layout
    const int tr  = tid >> 4;
    const int tc  = tid & 15;
    const int m0  = blockIdx.x * BM;

    float acc[TM][TN];
    #pragma unroll
    for (int i = 0; i < TM; ++i)
        #pragma unroll
        for (int j = 0; j < TN; ++j) acc[i][j] = 0.0f;

    for (int k0 = 0; k0 < KTOT; k0 += BK) {
        #pragma unroll
        for (int t = 0; t < BM * BK / 256; ++t) {
            int idx = tid + t * 256;
            int r = idx / BK, kk = idx % BK;
            int gr = m0 + r;
            As[r][kk] = (gr < M) ? A[(size_t)gr * KTOT + k0 + kk] : 0.0f;
        }
        #pragma unroll
        for (int t = 0; t < BK * BN / 256; ++t) {
            int idx = tid + t * 256;
            int kk = idx / BN, c = idx % BN;
            Bs[kk][c] = (c < NACT) ? B[(size_t)(k0 + kk) * NACT + c] : 0.0f;
        }
        __syncthreads();

        #pragma unroll
        for (int kk = 0; kk < BK; ++kk) {
            float a[TM], b[TN];
            #pragma unroll
            for (int i = 0; i < TM; ++i) a[i] = As[tr + i * 16][kk];
            #pragma unroll
            for (int j = 0; j < TN; ++j) b[j] = Bs[kk][tc + j * 16];
            #pragma unroll
            for (int i = 0; i < TM; ++i)
                #pragma unroll
                for (int j = 0; j < TN; ++j)
                    acc[i][j] += a[i] * b[j];
        }
        __syncthreads();
    }

    #pragma unroll
    for (int i = 0; i < TM; ++i) {
        int row = m0 + tr + i * 16;
        if (row >= M) continue;
        #pragma unroll
        for (int j = 0; j < TN; ++j) {
            int ccol = tc + j * 16;
            if (ccol < NACT)
                C[(size_t)row * NACT + ccol] = acc[i][j];
        }
    }
}

// ---------------------------------------------------------------------------
// Gather aggregation, F=128: one warp per destination node.
// out = relu( h[node]*dinv^2 + sum_in h[r]*coef + b1 )
// ---------------------------------------------------------------------------
__global__ void gather128_kernel(const float* __restrict__ h,
                                 const float* __restrict__ b,
                                 float* __restrict__ out)
{
    int node = (blockIdx.x * blockDim.x + threadIdx.x) >> 5;
    int lane = threadIdx.x & 31;
    if (node >= N_NODES) return;

    float g  = g_dinv[node];
    float gg = g * g;
    float4 acc = ((const float4*)(h + (size_t)node * F_HID))[lane];
    acc.x *= gg; acc.y *= gg; acc.z *= gg; acc.w *= gg;

    int e   = g_ptr[node];
    int end = g_ptr[node + 1];
    for (; e + 2 <= end; e += 2) {
        int   r0 = g_rows[e],     r1 = g_rows[e + 1];
        float c0 = g_coef[e],     c1 = g_coef[e + 1];
        float4 v0 = ((const float4*)(h + (size_t)r0 * F_HID))[lane];
        float4 v1 = ((const float4*)(h + (size_t)r1 * F_HID))[lane];
        acc.x += v0.x * c0 + v1.x * c1;
        acc.y += v0.y * c0 + v1.y * c1;
        acc.z += v0.z * c0 + v1.z * c1;
        acc.w += v0.w * c0 + v1.w * c1;
    }
    if (e < end) {
        int   r0 = g_rows[e];
        float c0 = g_coef[e];
        float4 v0 = ((const float4*)(h + (size_t)r0 * F_HID))[lane];
        acc.x += v0.x * c0; acc.y += v0.y * c0;
        acc.z += v0.z * c0; acc.w += v0.w * c0;
    }

    float4 bb = ((const float4*)b)[lane];
    acc.x = fmaxf(acc.x + bb.x, 0.0f);
    acc.y = fmaxf(acc.y + bb.y, 0.0f);
    acc.z = fmaxf(acc.z + bb.z, 0.0f);
    acc.w = fmaxf(acc.w + bb.w, 0.0f);
    ((float4*)(out + (size_t)node * F_HID))[lane] = acc;
}

// ---------------------------------------------------------------------------
// Gather aggregation, F=40: one warp per node; lane owns feature lane,
// lanes 0..7 also own feature 32+lane.
// out = h2[node]*dinv^2 + sum_in h2[r]*coef + b2
// ---------------------------------------------------------------------------
__global__ void gather40_kernel(const float* __restrict__ h,
                                const float* __restrict__ b,
                                float* __restrict__ out)
{
    int node = (blockIdx.x * blockDim.x + threadIdx.x) >> 5;
    int lane = threadIdx.x & 31;
    if (node >= N_NODES) return;

    bool has2 = lane < (F_OUT - 32);
    int  f1   = 32 + lane;

    float g  = g_dinv[node];
    float gg = g * g;
    const float* hn = h + (size_t)node * F_OUT;
    float a0 = hn[lane] * gg;
    float a1 = has2 ? hn[f1] * gg : 0.0f;

    int e   = g_ptr[node];
    int end = g_ptr[node + 1];
    for (; e < end; ++e) {
        int   r  = g_rows[e];
        float cf = g_coef[e];
        const float* hr = h + (size_t)r * F_OUT;
        a0 += hr[lane] * cf;
        if (has2) a1 += hr[f1] * cf;
    }

    float* o = out + (size_t)node * F_OUT;
    o[lane] = a0 + b[lane];
    if (has2) o[f1] = a1 + b[f1];
}

// ---------------------------------------------------------------------------
extern "C" void kernel_launch(void* const* d_in, const int* in_sizes, int n_in,
                              void* d_out, int out_size)
{
    const float* x   = (const float*)d_in[0];
    const int*   ei  = (const int*)d_in[1];      // int64 ref -> int32 on device
    const float* ew  = (const float*)d_in[2];
    const float* W1  = (const float*)d_in[3];
    const float* b1  = (const float*)d_in[4];
    const float* W2  = (const float*)d_in[5];
    const float* b2  = (const float*)d_in[6];
    float*       out = (float*)d_out;

    const int* row = ei;
    const int* col = ei + N_EDGES;

    float *p_h, *p_hrelu, *p_h2;
    cudaGetSymbolAddress((void**)&p_h,     g_h);
    cudaGetSymbolAddress((void**)&p_hrelu, g_hrelu);
    cudaGetSymbolAddress((void**)&p_h2,    g_h2);

    const int T = 256;
    const int GB_N = (N_NODES + T - 1) / T;
    const int GB_E = (N_EDGES + T - 1) / T;
    const int GB_W = (N_NODES * 32 + T - 1) / T;   // one warp per node

    // --- normalization + CSR build ---
    init_kernel <<<GB_N, T>>>();
    count_kernel<<<GB_E, T>>>(col, ew);
    dinv_kernel <<<GB_N, T>>>();
    scan1_kernel<<<NB, SCAN_B>>>();
    scan2_kernel<<<1,  SCAN_B>>>();
    scan3_kernel<<<GB_N, T>>>();
    fill_kernel <<<GB_E, T>>>(row, col, ew);

    // --- layer 1 ---
    gemm_kernel<64, 128, 32, F_IN, F_HID>
        <<<(N_NODES + 63) / 64, 256>>>(x, W1, p_h, N_NODES);
    gather128_kernel<<<GB_W, T>>>(p_h, b1, p_hrelu);

    // --- layer 2 ---
    gemm_kernel<64, 64, 32, F_HID, F_OUT>
        <<<(N_NODES + 63) / 64, 256>>>(p_hrelu, W2, p_h2, N_NODES);
    gather40_kernel<<<GB_W, T>>>(p_h2, b2, out);
}

// round 4
// speedup vs baseline: 3.0021x; 1.5238x over previous
#include <cuda_runtime.h>
#include <cstdint>

#define N_NODES 50000
#define N_EDGES 800000
#define F_IN    256
#define F_HID   128
#define F_OUT   40

#define SCAN_B  256
#define NB      ((N_NODES + SCAN_B - 1) / SCAN_B)   // 196

// Scratch (no allocation allowed anywhere)
__device__ float g_deg  [N_NODES];
__device__ float g_dinv [N_NODES];
__device__ int   g_cnt  [N_NODES];
__device__ int   g_ptr  [N_NODES + 1];
__device__ int   g_cur  [N_NODES];
__device__ int   g_bsum [NB];
__device__ int   g_boff [NB];
__device__ int   g_rows [N_EDGES];
__device__ float g_coef [N_EDGES];
__device__ float g_h    [N_NODES * F_HID];
__device__ float g_hrelu[N_NODES * F_HID];
__device__ float g_h2   [N_NODES * F_OUT];

// ---------------------------------------------------------------------------
// normalization + CSR build (unchanged from R3)
// ---------------------------------------------------------------------------
__global__ void init_kernel() {
    int i = blockIdx.x * blockDim.x + threadIdx.x;
    if (i < N_NODES) { g_deg[i] = 1.0f; g_cnt[i] = 0; }
}

__global__ void count_kernel(const int* __restrict__ col,
                             const float* __restrict__ ew) {
    int i = blockIdx.x * blockDim.x + threadIdx.x;
    if (i < N_EDGES) {
        int c = col[i];
        atomicAdd(&g_deg[c], ew[i]);
        atomicAdd(&g_cnt[c], 1);
    }
}

__global__ void dinv_kernel() {
    int i = blockIdx.x * blockDim.x + threadIdx.x;
    if (i < N_NODES) {
        float d = g_deg[i];
        g_dinv[i] = (d > 0.0f) ? rsqrtf(d) : 0.0f;
    }
}

__global__ void scan1_kernel() {
    __shared__ int s[SCAN_B];
    int i = blockIdx.x * SCAN_B + threadIdx.x;
    int v = (i < N_NODES) ? g_cnt[i] : 0;
    s[threadIdx.x] = v; __syncthreads();
    #pragma unroll
    for (int off = 1; off < SCAN_B; off <<= 1) {
        int t = (threadIdx.x >= off) ? s[threadIdx.x - off] : 0;
        __syncthreads();
        s[threadIdx.x] += t;
        __syncthreads();
    }
    if (i < N_NODES) g_ptr[i] = s[threadIdx.x] - v;
    if (threadIdx.x == SCAN_B - 1) g_bsum[blockIdx.x] = s[SCAN_B - 1];
}

__global__ void scan2_kernel() {
    __shared__ int s[SCAN_B];
    int v = (threadIdx.x < NB) ? g_bsum[threadIdx.x] : 0;
    s[threadIdx.x] = v; __syncthreads();
    #pragma unroll
    for (int off = 1; off < SCAN_B; off <<= 1) {
        int t = (threadIdx.x >= off) ? s[threadIdx.x - off] : 0;
        __syncthreads();
        s[threadIdx.x] += t;
        __syncthreads();
    }
    if (threadIdx.x < NB) g_boff[threadIdx.x] = s[threadIdx.x] - v;
}

__global__ void scan3_kernel() {
    int i = blockIdx.x * blockDim.x + threadIdx.x;
    if (i < N_NODES) {
        int p = g_ptr[i] + g_boff[i / SCAN_B];
        g_ptr[i] = p;
        g_cur[i] = p;
    }
    if (i == 0) g_ptr[N_NODES] = N_EDGES;
}

__global__ void fill_kernel(const int* __restrict__ row,
                            const int* __restrict__ col,
                            const float* __restrict__ ew) {
    int e = blockIdx.x * blockDim.x + threadIdx.x;
    if (e < N_EDGES) {
        int c = col[e], r = row[e];
        int pos = atomicAdd(&g_cur[c], 1);
        g_rows[pos] = r;
        g_coef[pos] = g_dinv[r] * ew[e] * g_dinv[c];
    }
}

// ---------------------------------------------------------------------------
// TF32 tensor-core GEMM: C = A[M,KTOT] @ B[KTOT,NACT]
// mma.sync.aligned.m16n8k8.row.col.f32.tf32.tf32.f32
// Block: 256 threads = 8 warps (4 along M x 2 along N).
// ---------------------------------------------------------------------------
__device__ __forceinline__ float to_tf32(float x) {
    uint32_t u;
    asm("cvt.rna.tf32.f32 %0, %1;" : "=r"(u) : "f"(x));
    return __uint_as_float(u);
}

__device__ __forceinline__ void mma_tf32(float* d, const uint32_t* a, const uint32_t* b) {
    asm volatile(
        "mma.sync.aligned.m16n8k8.row.col.f32.tf32.tf32.f32 "
        "{%0,%1,%2,%3}, {%4,%5,%6,%7}, {%8,%9}, {%0,%1,%2,%3};"
        : "+f"(d[0]), "+f"(d[1]), "+f"(d[2]), "+f"(d[3])
        : "r"(a[0]), "r"(a[1]), "r"(a[2]), "r"(a[3]),
          "r"(b[0]), "r"(b[1]));
}

template<int BM, int BN, int BK, int NACT, int KTOT>
__global__ void gemm_tf32_kernel(const float* __restrict__ A,
                                 const float* __restrict__ B,
                                 float* __restrict__ C, int M)
{
    constexpr int WM      = 32;
    constexpr int WARPS_M = BM / WM;         // 4
    constexpr int WARPS_N = 8 / WARPS_M;     // 2
    constexpr int WN      = BN / WARPS_N;
    constexpr int M16     = WM / 16;         // 2
    constexpr int N8      = WN / 8;
    constexpr int ITERS   = KTOT / BK;
    constexpr int AKQ     = BK / 4;          // float4 per A row
    constexpr int ALOADS  = BM * BK / (256 * 4);
    constexpr int BNQ     = BN / 4;
    constexpr int BLOADS  = BK * BN / (256 * 4);

    __shared__ float As[BK][BM + 1];
    __shared__ float Bs[BK][BN + 4];

    const int tid  = threadIdx.x;
    const int wid  = tid >> 5;
    const int lane = tid & 31;
    const int gid  = lane >> 2;      // group id (0..7)
    const int tig  = lane & 3;       // thread in group (0..3)
    const int wm   = wid % WARPS_M;
    const int wn   = wid / WARPS_M;
    const int m0   = blockIdx.x * BM;

    float4 aReg[ALOADS], bReg[BLOADS];

    auto ldg = [&](int it) {
        #pragma unroll
        for (int j = 0; j < ALOADS; ++j) {
            int f = j * 256 + tid;
            int m = f / AKQ, kq = f % AKQ;
            int gr = m0 + m;
            if (gr < M)
                aReg[j] = *(const float4*)(A + (size_t)gr * KTOT + it * BK + kq * 4);
            else
                aReg[j] = make_float4(0.f, 0.f, 0.f, 0.f);
        }
        #pragma unroll
        for (int j = 0; j < BLOADS; ++j) {
            int f = j * 256 + tid;
            int k = f / BNQ, nq = f % BNQ;
            if (NACT == BN) {
                bReg[j] = *(const float4*)(B + (size_t)(it * BK + k) * NACT + nq * 4);
            } else {
                float v[4];
                #pragma unroll
                for (int e = 0; e < 4; ++e) {
                    int n = nq * 4 + e;
                    v[e] = (n < NACT) ? B[(size_t)(it * BK + k) * NACT + n] : 0.f;
                }
                bReg[j] = make_float4(v[0], v[1], v[2], v[3]);
            }
        }
    };

    auto sts = [&]() {
        #pragma unroll
        for (int j = 0; j < ALOADS; ++j) {
            int f = j * 256 + tid;
            int m = f / AKQ, kq = f % AKQ;
            As[kq * 4 + 0][m] = to_tf32(aReg[j].x);
            As[kq * 4 + 1][m] = to_tf32(aReg[j].y);
            As[kq * 4 + 2][m] = to_tf32(aReg[j].z);
            As[kq * 4 + 3][m] = to_tf32(aReg[j].w);
        }
        #pragma unroll
        for (int j = 0; j < BLOADS; ++j) {
            int f = j * 256 + tid;
            int k = f / BNQ, nq = f % BNQ;
            float4 t;
            t.x = to_tf32(bReg[j].x);
            t.y = to_tf32(bReg[j].y);
            t.z = to_tf32(bReg[j].z);
            t.w = to_tf32(bReg[j].w);
            *(float4*)&Bs[k][nq * 4] = t;
        }
    };

    float acc[M16][N8][4];
    #pragma unroll
    for (int mi = 0; mi < M16; ++mi)
        #pragma unroll
        for (int ni = 0; ni < N8; ++ni)
            #pragma unroll
            for (int e = 0; e < 4; ++e)
                acc[mi][ni][e] = 0.f;

    ldg(0);
    sts();
    __syncthreads();

    for (int it = 0; it < ITERS; ++it) {
        if (it + 1 < ITERS) ldg(it + 1);

        #pragma unroll
        for (int kk = 0; kk < BK; kk += 8) {
            uint32_t af[M16][4];
            uint32_t bf[N8][2];
            #pragma unroll
            for (int mi = 0; mi < M16; ++mi) {
                int mb = wm * WM + mi * 16;
                af[mi][0] = __float_as_uint(As[kk + tig    ][mb + gid    ]);
                af[mi][1] = __float_as_uint(As[kk + tig    ][mb + gid + 8]);
                af[mi][2] = __float_as_uint(As[kk + tig + 4][mb + gid    ]);
                af[mi][3] = __float_as_uint(As[kk + tig + 4][mb + gid + 8]);
            }
            #pragma unroll
            for (int ni = 0; ni < N8; ++ni) {
                int nb = wn * WN + ni * 8;
                bf[ni][0] = __float_as_uint(Bs[kk + tig    ][nb + gid]);
                bf[ni][1] = __float_as_uint(Bs[kk + tig + 4][nb + gid]);
            }
            #pragma unroll
            for (int mi = 0; mi < M16; ++mi)
                #pragma unroll
                for (int ni = 0; ni < N8; ++ni)
                    mma_tf32(acc[mi][ni], af[mi], bf[ni]);
        }

        __syncthreads();
        if (it + 1 < ITERS) {
            sts();
            __syncthreads();
        }
    }

    // store D: d0:(gid, tig*2) d1:(gid, tig*2+1) d2:(gid+8, ...) d3
    #pragma unroll
    for (int mi = 0; mi < M16; ++mi) {
        #pragma unroll
        for (int ni = 0; ni < N8; ++ni) {
            int col = wn * WN + ni * 8 + tig * 2;
            if (col >= NACT) continue;
            int r0 = m0 + wm * WM + mi * 16 + gid;
            int r1 = r0 + 8;
            if (r0 < M)
                *(float2*)(C + (size_t)r0 * NACT + col) = make_float2(acc[mi][ni][0], acc[mi][ni][1]);
            if (r1 < M)
                *(float2*)(C + (size_t)r1 * NACT + col) = make_float2(acc[mi][ni][2], acc[mi][ni][3]);
        }
    }
}

// ---------------------------------------------------------------------------
// Gather aggregation (unchanged from R3)
// ---------------------------------------------------------------------------
__global__ void gather128_kernel(const float* __restrict__ h,
                                 const float* __restrict__ b,
                                 float* __restrict__ out)
{
    int node = (blockIdx.x * blockDim.x + threadIdx.x) >> 5;
    int lane = threadIdx.x & 31;
    if (node >= N_NODES) return;

    float g  = g_dinv[node];
    float gg = g * g;
    float4 acc = ((const float4*)(h + (size_t)node * F_HID))[lane];
    acc.x *= gg; acc.y *= gg; acc.z *= gg; acc.w *= gg;

    int e   = g_ptr[node];
    int end = g_ptr[node + 1];
    for (; e + 2 <= end; e += 2) {
        int   r0 = g_rows[e],     r1 = g_rows[e + 1];
        float c0 = g_coef[e],     c1 = g_coef[e + 1];
        float4 v0 = ((const float4*)(h + (size_t)r0 * F_HID))[lane];
        float4 v1 = ((const float4*)(h + (size_t)r1 * F_HID))[lane];
        acc.x += v0.x * c0 + v1.x * c1;
        acc.y += v0.y * c0 + v1.y * c1;
        acc.z += v0.z * c0 + v1.z * c1;
        acc.w += v0.w * c0 + v1.w * c1;
    }
    if (e < end) {
        int   r0 = g_rows[e];
        float c0 = g_coef[e];
        float4 v0 = ((const float4*)(h + (size_t)r0 * F_HID))[lane];
        acc.x += v0.x * c0; acc.y += v0.y * c0;
        acc.z += v0.z * c0; acc.w += v0.w * c0;
    }

    float4 bb = ((const float4*)b)[lane];
    acc.x = fmaxf(acc.x + bb.x, 0.0f);
    acc.y = fmaxf(acc.y + bb.y, 0.0f);
    acc.z = fmaxf(acc.z + bb.z, 0.0f);
    acc.w = fmaxf(acc.w + bb.w, 0.0f);
    ((float4*)(out + (size_t)node * F_HID))[lane] = acc;
}

__global__ void gather40_kernel(const float* __restrict__ h,
                                const float* __restrict__ b,
                                float* __restrict__ out)
{
    int node = (blockIdx.x * blockDim.x + threadIdx.x) >> 5;
    int lane = threadIdx.x & 31;
    if (node >= N_NODES) return;

    bool has2 = lane < (F_OUT - 32);
    int  f1   = 32 + lane;

    float g  = g_dinv[node];
    float gg = g * g;
    const float* hn = h + (size_t)node * F_OUT;
    float a0 = hn[lane] * gg;
    float a1 = has2 ? hn[f1] * gg : 0.0f;

    int e   = g_ptr[node];
    int end = g_ptr[node + 1];
    for (; e < end; ++e) {
        int   r  = g_rows[e];
        float cf = g_coef[e];
        const float* hr = h + (size_t)r * F_OUT;
        a0 += hr[lane] * cf;
        if (has2) a1 += hr[f1] * cf;
    }

    float* o = out + (size_t)node * F_OUT;
    o[lane] = a0 + b[lane];
    if (has2) o[f1] = a1 + b[f1];
}

// ---------------------------------------------------------------------------
extern "C" void kernel_launch(void* const* d_in, const int* in_sizes, int n_in,
                              void* d_out, int out_size)
{
    const float* x   = (const float*)d_in[0];
    const int*   ei  = (const int*)d_in[1];      // int64 ref -> int32 on device
    const float* ew  = (const float*)d_in[2];
    const float* W1  = (const float*)d_in[3];
    const float* b1  = (const float*)d_in[4];
    const float* W2  = (const float*)d_in[5];
    const float* b2  = (const float*)d_in[6];
    float*       out = (float*)d_out;

    const int* row = ei;
    const int* col = ei + N_EDGES;

    float *p_h, *p_hrelu, *p_h2;
    cudaGetSymbolAddress((void**)&p_h,     g_h);
    cudaGetSymbolAddress((void**)&p_hrelu, g_hrelu);
    cudaGetSymbolAddress((void**)&p_h2,    g_h2);

    const int T = 256;
    const int GB_N = (N_NODES + T - 1) / T;
    const int GB_E = (N_EDGES + T - 1) / T;
    const int GB_W = (N_NODES * 32 + T - 1) / T;

    // --- normalization + CSR build ---
    init_kernel <<<GB_N, T>>>();
    count_kernel<<<GB_E, T>>>(col, ew);
    dinv_kernel <<<GB_N, T>>>();
    scan1_kernel<<<NB, SCAN_B>>>();
    scan2_kernel<<<1,  SCAN_B>>>();
    scan3_kernel<<<GB_N, T>>>();
    fill_kernel <<<GB_E, T>>>(row, col, ew);

    const int GEMM_GRID = (N_NODES + 127) / 128;

    // --- layer 1: h = x @ W1 (tf32 tensor cores) ---
    gemm_tf32_kernel<128, 128, 32, F_HID, F_IN>
        <<<GEMM_GRID, 256>>>(x, W1, p_h, N_NODES);
    gather128_kernel<<<GB_W, T>>>(p_h, b1, p_hrelu);

    // --- layer 2: h2 = relu(agg1) @ W2 (tf32 tensor cores) ---
    gemm_tf32_kernel<128, 64, 32, F_OUT, F_HID>
        <<<GEMM_GRID, 256>>>(p_hrelu, W2, p_h2, N_NODES);
    gather40_kernel<<<GB_W, T>>>(p_h2, b2, out);
}

// round 5
// speedup vs baseline: 3.3574x; 1.1184x over previous
#include <cuda_runtime.h>
#include <cstdint>

#define N_NODES 50000
#define N_EDGES 800000
#define F_IN    256
#define F_HID   128
#define F_OUT   40

#define SCAN_B  256
#define NB      ((N_NODES + SCAN_B - 1) / SCAN_B)   // 196

// Scratch (no allocation allowed anywhere)
__device__ float g_deg  [N_NODES];
__device__ float g_dinv [N_NODES];
__device__ int   g_cnt  [N_NODES];
__device__ int   g_ptr  [N_NODES + 1];
__device__ int   g_cur  [N_NODES];
__device__ int   g_bsum [NB];
__device__ int   g_boff [NB];
__device__ int   g_rows [N_EDGES];
__device__ float g_coef [N_EDGES];
__device__ float g_h    [N_NODES * F_HID];
__device__ float g_hrelu[N_NODES * F_HID];
__device__ float g_h2   [N_NODES * F_OUT];

// ---------------------------------------------------------------------------
// CSR build branch (runs on forked stream, overlapped with GEMM1)
// ---------------------------------------------------------------------------
__global__ void init_kernel() {
    int i = blockIdx.x * blockDim.x + threadIdx.x;
    if (i < N_NODES) { g_deg[i] = 1.0f; g_cnt[i] = 0; }
}

__global__ void count_kernel(const int* __restrict__ col,
                             const float* __restrict__ ew) {
    int i = blockIdx.x * blockDim.x + threadIdx.x;
    if (i < N_EDGES) {
        int c = col[i];
        atomicAdd(&g_deg[c], ew[i]);
        atomicAdd(&g_cnt[c], 1);
    }
}

// block-level exclusive scan of g_cnt (warp-shuffle) + fused dinv
__global__ void scan1_kernel() {
    const int i    = blockIdx.x * SCAN_B + threadIdx.x;
    const int lane = threadIdx.x & 31;
    const int wid  = threadIdx.x >> 5;

    int v = (i < N_NODES) ? g_cnt[i] : 0;
    if (i < N_NODES) {
        float d = g_deg[i];
        g_dinv[i] = (d > 0.0f) ? rsqrtf(d) : 0.0f;
    }

    int x = v;
    #pragma unroll
    for (int o = 1; o < 32; o <<= 1) {
        int t = __shfl_up_sync(0xffffffffu, x, o);
        if (lane >= o) x += t;
    }
    __shared__ int wsum[8];
    if (lane == 31) wsum[wid] = x;
    __syncthreads();
    if (wid == 0) {
        int w = (lane < 8) ? wsum[lane] : 0;
        #pragma unroll
        for (int o = 1; o < 8; o <<= 1) {
            int t = __shfl_up_sync(0xffffffffu, w, o);
            if (lane >= o) w += t;
        }
        if (lane < 8) wsum[lane] = w;
    }
    __syncthreads();
    int incl = x + (wid > 0 ? wsum[wid - 1] : 0);
    if (i < N_NODES) g_ptr[i] = incl - v;                 // exclusive
    if (threadIdx.x == SCAN_B - 1) g_bsum[blockIdx.x] = incl;
}

// single-block shuffle scan of the NB block sums
__global__ void scan2_kernel() {
    const int t    = threadIdx.x;
    const int lane = t & 31;
    const int wid  = t >> 5;
    int v = (t < NB) ? g_bsum[t] : 0;
    int x = v;
    #pragma unroll
    for (int o = 1; o < 32; o <<= 1) {
        int tt = __shfl_up_sync(0xffffffffu, x, o);
        if (lane >= o) x += tt;
    }
    __shared__ int wsum[8];
    if (lane == 31) wsum[wid] = x;
    __syncthreads();
    if (wid == 0) {
        int w = (lane < 8) ? wsum[lane] : 0;
        #pragma unroll
        for (int o = 1; o < 8; o <<= 1) {
            int tt = __shfl_up_sync(0xffffffffu, w, o);
            if (lane >= o) w += tt;
        }
        if (lane < 8) wsum[lane] = w;
    }
    __syncthreads();
    int incl = x + (wid > 0 ? wsum[wid - 1] : 0);
    if (t < NB) g_boff[t] = incl - v;
}

__global__ void scan3_kernel() {
    int i = blockIdx.x * blockDim.x + threadIdx.x;
    if (i < N_NODES) {
        int p = g_ptr[i] + g_boff[i / SCAN_B];
        g_ptr[i] = p;
        g_cur[i] = p;
    }
    if (i == 0) g_ptr[N_NODES] = N_EDGES;
}

__global__ void fill_kernel(const int* __restrict__ row,
                            const int* __restrict__ col,
                            const float* __restrict__ ew) {
    int e = blockIdx.x * blockDim.x + threadIdx.x;
    if (e < N_EDGES) {
        int c = col[e], r = row[e];
        int pos = atomicAdd(&g_cur[c], 1);
        g_rows[pos] = r;
        g_coef[pos] = g_dinv[r] * ew[e] * g_dinv[c];
    }
}

// ---------------------------------------------------------------------------
// TF32 tensor-core GEMM (as in R4)
// ---------------------------------------------------------------------------
__device__ __forceinline__ float to_tf32(float x) {
    uint32_t u;
    asm("cvt.rna.tf32.f32 %0, %1;" : "=r"(u) : "f"(x));
    return __uint_as_float(u);
}

__device__ __forceinline__ void mma_tf32(float* d, const uint32_t* a, const uint32_t* b) {
    asm volatile(
        "mma.sync.aligned.m16n8k8.row.col.f32.tf32.tf32.f32 "
        "{%0,%1,%2,%3}, {%4,%5,%6,%7}, {%8,%9}, {%0,%1,%2,%3};"
        : "+f"(d[0]), "+f"(d[1]), "+f"(d[2]), "+f"(d[3])
        : "r"(a[0]), "r"(a[1]), "r"(a[2]), "r"(a[3]),
          "r"(b[0]), "r"(b[1]));
}

template<int BM, int BN, int BK, int NACT, int KTOT>
__global__ void gemm_tf32_kernel(const float* __restrict__ A,
                                 const float* __restrict__ B,
                                 float* __restrict__ C, int M)
{
    constexpr int WM      = 32;
    constexpr int WARPS_M = BM / WM;         // 4
    constexpr int WARPS_N = 8 / WARPS_M;     // 2
    constexpr int WN      = BN / WARPS_N;
    constexpr int M16     = WM / 16;         // 2
    constexpr int N8      = WN / 8;
    constexpr int ITERS   = KTOT / BK;
    constexpr int AKQ     = BK / 4;
    constexpr int ALOADS  = BM * BK / (256 * 4);
    constexpr int BNQ     = BN / 4;
    constexpr int BLOADS  = BK * BN / (256 * 4);

    __shared__ float As[BK][BM + 1];
    __shared__ float Bs[BK][BN + 4];

    const int tid  = threadIdx.x;
    const int wid  = tid >> 5;
    const int lane = tid & 31;
    const int gid  = lane >> 2;
    const int tig  = lane & 3;
    const int wm   = wid % WARPS_M;
    const int wn   = wid / WARPS_M;
    const int m0   = blockIdx.x * BM;

    float4 aReg[ALOADS], bReg[BLOADS];

    auto ldg = [&](int it) {
        #pragma unroll
        for (int j = 0; j < ALOADS; ++j) {
            int f = j * 256 + tid;
            int m = f / AKQ, kq = f % AKQ;
            int gr = m0 + m;
            if (gr < M)
                aReg[j] = *(const float4*)(A + (size_t)gr * KTOT + it * BK + kq * 4);
            else
                aReg[j] = make_float4(0.f, 0.f, 0.f, 0.f);
        }
        #pragma unroll
        for (int j = 0; j < BLOADS; ++j) {
            int f = j * 256 + tid;
            int k = f / BNQ, nq = f % BNQ;
            if (NACT == BN) {
                bReg[j] = *(const float4*)(B + (size_t)(it * BK + k) * NACT + nq * 4);
            } else {
                float v[4];
                #pragma unroll
                for (int e = 0; e < 4; ++e) {
                    int n = nq * 4 + e;
                    v[e] = (n < NACT) ? B[(size_t)(it * BK + k) * NACT + n] : 0.f;
                }
                bReg[j] = make_float4(v[0], v[1], v[2], v[3]);
            }
        }
    };

    auto sts = [&]() {
        #pragma unroll
        for (int j = 0; j < ALOADS; ++j) {
            int f = j * 256 + tid;
            int m = f / AKQ, kq = f % AKQ;
            As[kq * 4 + 0][m] = to_tf32(aReg[j].x);
            As[kq * 4 + 1][m] = to_tf32(aReg[j].y);
            As[kq * 4 + 2][m] = to_tf32(aReg[j].z);
            As[kq * 4 + 3][m] = to_tf32(aReg[j].w);
        }
        #pragma unroll
        for (int j = 0; j < BLOADS; ++j) {
            int f = j * 256 + tid;
            int k = f / BNQ, nq = f % BNQ;
            float4 t;
            t.x = to_tf32(bReg[j].x);
            t.y = to_tf32(bReg[j].y);
            t.z = to_tf32(bReg[j].z);
            t.w = to_tf32(bReg[j].w);
            *(float4*)&Bs[k][nq * 4] = t;
        }
    };

    float acc[M16][N8][4];
    #pragma unroll
    for (int mi = 0; mi < M16; ++mi)
        #pragma unroll
        for (int ni = 0; ni < N8; ++ni)
            #pragma unroll
            for (int e = 0; e < 4; ++e)
                acc[mi][ni][e] = 0.f;

    ldg(0);
    sts();
    __syncthreads();

    for (int it = 0; it < ITERS; ++it) {
        if (it + 1 < ITERS) ldg(it + 1);

        #pragma unroll
        for (int kk = 0; kk < BK; kk += 8) {
            uint32_t af[M16][4];
            uint32_t bf[N8][2];
            #pragma unroll
            for (int mi = 0; mi < M16; ++mi) {
                int mb = wm * WM + mi * 16;
                af[mi][0] = __float_as_uint(As[kk + tig    ][mb + gid    ]);
                af[mi][1] = __float_as_uint(As[kk + tig    ][mb + gid + 8]);
                af[mi][2] = __float_as_uint(As[kk + tig + 4][mb + gid    ]);
                af[mi][3] = __float_as_uint(As[kk + tig + 4][mb + gid + 8]);
            }
            #pragma unroll
            for (int ni = 0; ni < N8; ++ni) {
                int nb = wn * WN + ni * 8;
                bf[ni][0] = __float_as_uint(Bs[kk + tig    ][nb + gid]);
                bf[ni][1] = __float_as_uint(Bs[kk + tig + 4][nb + gid]);
            }
            #pragma unroll
            for (int mi = 0; mi < M16; ++mi)
                #pragma unroll
                for (int ni = 0; ni < N8; ++ni)
                    mma_tf32(acc[mi][ni], af[mi], bf[ni]);
        }

        __syncthreads();
        if (it + 1 < ITERS) {
            sts();
            __syncthreads();
        }
    }

    #pragma unroll
    for (int mi = 0; mi < M16; ++mi) {
        #pragma unroll
        for (int ni = 0; ni < N8; ++ni) {
            int col = wn * WN + ni * 8 + tig * 2;
            if (col >= NACT) continue;
            int r0 = m0 + wm * WM + mi * 16 + gid;
            int r1 = r0 + 8;
            if (r0 < M)
                *(float2*)(C + (size_t)r0 * NACT + col) = make_float2(acc[mi][ni][0], acc[mi][ni][1]);
            if (r1 < M)
                *(float2*)(C + (size_t)r1 * NACT + col) = make_float2(acc[mi][ni][2], acc[mi][ni][3]);
        }
    }
}

// ---------------------------------------------------------------------------
// Gather aggregation
// ---------------------------------------------------------------------------
__global__ void gather128_kernel(const float* __restrict__ h,
                                 const float* __restrict__ b,
                                 float* __restrict__ out)
{
    int node = (blockIdx.x * blockDim.x + threadIdx.x) >> 5;
    int lane = threadIdx.x & 31;
    if (node >= N_NODES) return;

    float g  = g_dinv[node];
    float gg = g * g;
    float4 acc = ((const float4*)(h + (size_t)node * F_HID))[lane];
    acc.x *= gg; acc.y *= gg; acc.z *= gg; acc.w *= gg;

    int e   = g_ptr[node];
    int end = g_ptr[node + 1];
    for (; e + 2 <= end; e += 2) {
        int   r0 = g_rows[e],     r1 = g_rows[e + 1];
        float c0 = g_coef[e],     c1 = g_coef[e + 1];
        float4 v0 = ((const float4*)(h + (size_t)r0 * F_HID))[lane];
        float4 v1 = ((const float4*)(h + (size_t)r1 * F_HID))[lane];
        acc.x += v0.x * c0 + v1.x * c1;
        acc.y += v0.y * c0 + v1.y * c1;
        acc.z += v0.z * c0 + v1.z * c1;
        acc.w += v0.w * c0 + v1.w * c1;
    }
    if (e < end) {
        int   r0 = g_rows[e];
        float c0 = g_coef[e];
        float4 v0 = ((const float4*)(h + (size_t)r0 * F_HID))[lane];
        acc.x += v0.x * c0; acc.y += v0.y * c0;
        acc.z += v0.z * c0; acc.w += v0.w * c0;
    }

    float4 bb = ((const float4*)b)[lane];
    acc.x = fmaxf(acc.x + bb.x, 0.0f);
    acc.y = fmaxf(acc.y + bb.y, 0.0f);
    acc.z = fmaxf(acc.z + bb.z, 0.0f);
    acc.w = fmaxf(acc.w + bb.w, 0.0f);
    ((float4*)(out + (size_t)node * F_HID))[lane] = acc;
}

__global__ void gather40_kernel(const float* __restrict__ h,
                                const float* __restrict__ b,
                                float* __restrict__ out)
{
    int node = (blockIdx.x * blockDim.x + threadIdx.x) >> 5;
    int lane = threadIdx.x & 31;
    if (node >= N_NODES) return;

    bool has2 = lane < (F_OUT - 32);
    int  f1   = 32 + lane;

    float g  = g_dinv[node];
    float gg = g * g;
    const float* hn = h + (size_t)node * F_OUT;
    float a0 = hn[lane] * gg;
    float a1 = has2 ? hn[f1] * gg : 0.0f;

    int e   = g_ptr[node];
    int end = g_ptr[node + 1];
    for (; e < end; ++e) {
        int   r  = g_rows[e];
        float cf = g_coef[e];
        const float* hr = h + (size_t)r * F_OUT;
        a0 += hr[lane] * cf;
        if (has2) a1 += hr[f1] * cf;
    }

    float* o = out + (size_t)node * F_OUT;
    o[lane] = a0 + b[lane];
    if (has2) o[f1] = a1 + b[f1];
}

// ---------------------------------------------------------------------------
extern "C" void kernel_launch(void* const* d_in, const int* in_sizes, int n_in,
                              void* d_out, int out_size)
{
    const float* x   = (const float*)d_in[0];
    const int*   ei  = (const int*)d_in[1];      // int64 ref -> int32 on device
    const float* ew  = (const float*)d_in[2];
    const float* W1  = (const float*)d_in[3];
    const float* b1  = (const float*)d_in[4];
    const float* W2  = (const float*)d_in[5];
    const float* b2  = (const float*)d_in[6];
    float*       out = (float*)d_out;

    const int* row = ei;
    const int* col = ei + N_EDGES;

    float *p_h, *p_hrelu, *p_h2;
    cudaGetSymbolAddress((void**)&p_h,     g_h);
    cudaGetSymbolAddress((void**)&p_hrelu, g_hrelu);
    cudaGetSymbolAddress((void**)&p_h2,    g_h2);

    const int T = 256;
    const int GB_N = (N_NODES + T - 1) / T;
    const int GB_E = (N_EDGES + T - 1) / T;
    const int GB_W = (N_NODES * 32 + T - 1) / T;
    const int GEMM_GRID = (N_NODES + 127) / 128;

    // Fork a worker stream so the CSR build overlaps GEMM1.
    // (Stream/event creation is an immediate host API — not a captured op;
    //  the record/wait pairs become graph dependencies.)
    cudaStream_t s1;
    cudaEvent_t  eFork, eJoin;
    cudaStreamCreateWithFlags(&s1, cudaStreamNonBlocking);
    cudaEventCreateWithFlags(&eFork, cudaEventDisableTiming);
    cudaEventCreateWithFlags(&eJoin, cudaEventDisableTiming);

    cudaEventRecord(eFork, 0);
    cudaStreamWaitEvent(s1, eFork, 0);

    // --- CSR build branch (stream s1) ---
    init_kernel <<<GB_N, T, 0, s1>>>();
    count_kernel<<<GB_E, T, 0, s1>>>(col, ew);
    scan1_kernel<<<NB, SCAN_B, 0, s1>>>();          // + fused dinv
    scan2_kernel<<<1,  SCAN_B, 0, s1>>>();
    scan3_kernel<<<GB_N, T, 0, s1>>>();
    fill_kernel <<<GB_E, T, 0, s1>>>(row, col, ew);
    cudaEventRecord(eJoin, s1);

    // --- GEMM1 concurrently on the origin stream ---
    gemm_tf32_kernel<128, 128, 32, F_HID, F_IN>
        <<<GEMM_GRID, 256>>>(x, W1, p_h, N_NODES);

    // join: gather needs both GEMM1 and the CSR
    cudaStreamWaitEvent(0, eJoin, 0);

    gather128_kernel<<<GB_W, T>>>(p_h, b1, p_hrelu);

    gemm_tf32_kernel<128, 64, 32, F_OUT, F_HID>
        <<<GEMM_GRID, 256>>>(p_hrelu, W2, p_h2, N_NODES);
    gather40_kernel<<<GB_W, T>>>(p_h2, b2, out);
}